// round 1
// baseline (speedup 1.0000x reference)
#include <cuda_runtime.h>
#include <cstdint>

// Problem constants
#define B_   2
#define T_   4096
#define D_   512
#define H_   8
#define HD_  64
#define M_   (B_ * T_)        // 8192
#define N3_  (3 * D_)         // 1536

// Scratch (static device globals — no allocation in kernel_launch)
__device__ float g_qkv[M_ * N3_];   // [8192, 1536] q|k|v
__device__ float g_att[M_ * D_];    // [8192, 512]  attention output (b t (h d))

// ---------------------------------------------------------------------------
// Generic NT GEMM: C[m,n] = sum_k A[m,k] * B[n,k]
// 64x64 tile, BK=16, 256 threads, 4x4 register blocking. M,N,K all multiples
// of tile sizes for this problem, so no bounds checks.
// ---------------------------------------------------------------------------
__device__ __forceinline__ void gemm_nt_dev(const float* __restrict__ A,
                                            const float* __restrict__ Bm,
                                            float* __restrict__ C,
                                            int N, int K) {
    __shared__ float As[64][17];
    __shared__ float Bs[64][17];

    const int tid = threadIdx.x;
    const int ty = tid >> 4;          // 0..15
    const int tx = tid & 15;          // 0..15
    const int m0 = blockIdx.y * 64;
    const int n0 = blockIdx.x * 64;

    const int lr = tid >> 2;          // 0..63 (tile row for loads)
    const int lc = (tid & 3) << 2;    // 0,4,8,12 (k offset for loads)

    const float* Ap = A + (size_t)(m0 + lr) * K + lc;
    const float* Bp = Bm + (size_t)(n0 + lr) * K + lc;

    float acc[4][4] = {};

    for (int k0 = 0; k0 < K; k0 += 16) {
        const float4 av = *reinterpret_cast<const float4*>(Ap + k0);
        const float4 bv = *reinterpret_cast<const float4*>(Bp + k0);
        __syncthreads();
        As[lr][lc + 0] = av.x; As[lr][lc + 1] = av.y;
        As[lr][lc + 2] = av.z; As[lr][lc + 3] = av.w;
        Bs[lr][lc + 0] = bv.x; Bs[lr][lc + 1] = bv.y;
        Bs[lr][lc + 2] = bv.z; Bs[lr][lc + 3] = bv.w;
        __syncthreads();

#pragma unroll
        for (int k = 0; k < 16; ++k) {
            float a_[4], b_[4];
#pragma unroll
            for (int i = 0; i < 4; ++i) a_[i] = As[ty * 4 + i][k];
#pragma unroll
            for (int j = 0; j < 4; ++j) b_[j] = Bs[tx * 4 + j][k];
#pragma unroll
            for (int i = 0; i < 4; ++i)
#pragma unroll
                for (int j = 0; j < 4; ++j)
                    acc[i][j] = fmaf(a_[i], b_[j], acc[i][j]);
        }
    }

#pragma unroll
    for (int i = 0; i < 4; ++i) {
        float4 v = make_float4(acc[i][0], acc[i][1], acc[i][2], acc[i][3]);
        *reinterpret_cast<float4*>(C + (size_t)(m0 + ty * 4 + i) * N + n0 + tx * 4) = v;
    }
}

__global__ void __launch_bounds__(256)
gemm_qkv_kernel(const float* __restrict__ x, const float* __restrict__ w) {
    gemm_nt_dev(x, w, g_qkv, N3_, D_);
}

__global__ void __launch_bounds__(256)
gemm_out_kernel(const float* __restrict__ w, float* __restrict__ out) {
    gemm_nt_dev(g_att, w, out, D_, D_);
}

// ---------------------------------------------------------------------------
// Flash attention (causal), fp32. One block handles one (b,h) x 64-row Q tile.
// 256 threads = 16x16 thread grid, each thread owns a 4x4 output tile.
// SMEM: Qs[64][64] (broadcast reads), KT[64][64] (transposed + XOR-swizzled K,
// reused for P after S is computed), Vs[64][64]. Exactly 48KB static.
// ---------------------------------------------------------------------------
__global__ void __launch_bounds__(256) flash_kernel() {
    __shared__ float Qs[64 * 64];
    __shared__ float KT[64 * 64];   // K^T swizzled; later reused as P [row][kk]
    __shared__ float Vs[64 * 64];

    const int tid = threadIdx.x;
    const int ty = tid >> 4;
    const int tx = tid & 15;

    // heavy q-tiles first (causal: qt=63 does 64 k-tiles)
    const int qt = (int)gridDim.y - 1 - (int)blockIdx.y;
    const int bh = blockIdx.x;
    const int b = bh >> 3;
    const int h = bh & 7;

    const float* qptr = g_qkv + (size_t)b * T_ * N3_ + h * HD_;
    const float* kptr = qptr + D_;
    const float* vptr = qptr + 2 * D_;

    const int q0 = qt * 64;
    const int r16 = tid >> 4;          // 0..15
    const int c4 = (tid & 15) << 2;    // 0..60 step 4

    // Load Q tile (pre-scaled by 1/sqrt(HD)=0.125)
#pragma unroll
    for (int rr = r16; rr < 64; rr += 16) {
        const float4 v = *reinterpret_cast<const float4*>(
            qptr + (size_t)(q0 + rr) * N3_ + c4);
        Qs[rr * 64 + c4 + 0] = v.x * 0.125f;
        Qs[rr * 64 + c4 + 1] = v.y * 0.125f;
        Qs[rr * 64 + c4 + 2] = v.z * 0.125f;
        Qs[rr * 64 + c4 + 3] = v.w * 0.125f;
    }

    float m_i[4], l_i[4], o[4][4];
#pragma unroll
    for (int i = 0; i < 4; ++i) {
        m_i[i] = -1e30f;
        l_i[i] = 0.0f;
#pragma unroll
        for (int j = 0; j < 4; ++j) o[i][j] = 0.0f;
    }

    for (int j0 = 0; j0 <= q0; j0 += 64) {
        __syncthreads();   // previous PV reads of Vs / first-iter Qs visibility

        // Load K (transposed, XOR-swizzled) and V tiles
#pragma unroll
        for (int rr = r16; rr < 64; rr += 16) {
            const float4 kv = *reinterpret_cast<const float4*>(
                kptr + (size_t)(j0 + rr) * N3_ + c4);
            const float4 vv = *reinterpret_cast<const float4*>(
                vptr + (size_t)(j0 + rr) * N3_ + c4);
            const float k4[4] = {kv.x, kv.y, kv.z, kv.w};
#pragma unroll
            for (int q = 0; q < 4; ++q) {
                const int d = c4 + q;
                const int g = (d >> 2) << 1;            // even, 0..30
                KT[d * 64 + (rr ^ g)] = k4[q];          // conflict-free store
            }
            Vs[rr * 64 + c4 + 0] = vv.x;
            Vs[rr * 64 + c4 + 1] = vv.y;
            Vs[rr * 64 + c4 + 2] = vv.z;
            Vs[rr * 64 + c4 + 3] = vv.w;
        }
        __syncthreads();

        // S = Q K^T
        float s[4][4] = {};
#pragma unroll 8
        for (int d = 0; d < 64; ++d) {
            const int g = (d >> 2) << 1;
            float a_[4], b_[4];
#pragma unroll
            for (int i = 0; i < 4; ++i) a_[i] = Qs[(ty * 4 + i) * 64 + d];
#pragma unroll
            for (int j = 0; j < 4; ++j) b_[j] = KT[d * 64 + ((tx * 4 + j) ^ g)];
#pragma unroll
            for (int i = 0; i < 4; ++i)
#pragma unroll
                for (int j = 0; j < 4; ++j)
                    s[i][j] = fmaf(a_[i], b_[j], s[i][j]);
        }

        // Causal mask on diagonal tile
        if (j0 == q0) {
#pragma unroll
            for (int i = 0; i < 4; ++i)
#pragma unroll
                for (int j = 0; j < 4; ++j)
                    if (tx * 4 + j > ty * 4 + i) s[i][j] = -1e30f;
        }

        // Online softmax: row-max / row-sum across 16 lanes (same ty group)
        float alpha[4];
#pragma unroll
        for (int i = 0; i < 4; ++i) {
            float v = fmaxf(fmaxf(s[i][0], s[i][1]), fmaxf(s[i][2], s[i][3]));
#pragma unroll
            for (int off = 8; off > 0; off >>= 1)
                v = fmaxf(v, __shfl_xor_sync(0xffffffffu, v, off));
            const float mn = fmaxf(m_i[i], v);
            alpha[i] = __expf(m_i[i] - mn);
            m_i[i] = mn;
        }
#pragma unroll
        for (int i = 0; i < 4; ++i) {
#pragma unroll
            for (int j = 0; j < 4; ++j) s[i][j] = __expf(s[i][j] - m_i[i]);
            float v = (s[i][0] + s[i][1]) + (s[i][2] + s[i][3]);
#pragma unroll
            for (int off = 8; off > 0; off >>= 1)
                v += __shfl_xor_sync(0xffffffffu, v, off);
            l_i[i] = l_i[i] * alpha[i] + v;
#pragma unroll
            for (int j = 0; j < 4; ++j) o[i][j] *= alpha[i];
        }

        __syncthreads();   // all K reads done before P overwrites KT
#pragma unroll
        for (int i = 0; i < 4; ++i)
#pragma unroll
            for (int j = 0; j < 4; ++j)
                KT[(ty * 4 + i) * 64 + tx * 4 + j] = s[i][j];
        __syncthreads();

        // O += P @ V
#pragma unroll 8
        for (int kk = 0; kk < 64; ++kk) {
            float a_[4], b_[4];
#pragma unroll
            for (int i = 0; i < 4; ++i) a_[i] = KT[(ty * 4 + i) * 64 + kk];
#pragma unroll
            for (int j = 0; j < 4; ++j) b_[j] = Vs[kk * 64 + tx * 4 + j];
#pragma unroll
            for (int i = 0; i < 4; ++i)
#pragma unroll
                for (int j = 0; j < 4; ++j)
                    o[i][j] = fmaf(a_[i], b_[j], o[i][j]);
        }
    }

    // Epilogue: normalize and store to g_att in (b, t, h*64+d) layout
#pragma unroll
    for (int i = 0; i < 4; ++i) {
        const float inv = 1.0f / l_i[i];
        float4 v = make_float4(o[i][0] * inv, o[i][1] * inv,
                               o[i][2] * inv, o[i][3] * inv);
        *reinterpret_cast<float4*>(
            g_att + ((size_t)(b * T_ + q0 + ty * 4 + i)) * D_ + h * HD_ + tx * 4) = v;
    }
}

// ---------------------------------------------------------------------------
extern "C" void kernel_launch(void* const* d_in, const int* in_sizes, int n_in,
                              void* d_out, int out_size) {
    // Map inputs by element count for robustness (x, w_qkv, w_out)
    const float* x = nullptr;
    const float* w_qkv = nullptr;
    const float* w_out = nullptr;
    for (int i = 0; i < n_in; ++i) {
        if (in_sizes[i] == M_ * D_)            x = (const float*)d_in[i];
        else if (in_sizes[i] == N3_ * D_)      w_qkv = (const float*)d_in[i];
        else if (in_sizes[i] == D_ * D_)       w_out = (const float*)d_in[i];
    }
    float* out = (float*)d_out;

    // 1) QKV projection: [8192,512] x [1536,512]^T -> g_qkv
    gemm_qkv_kernel<<<dim3(N3_ / 64, M_ / 64), 256>>>(x, w_qkv);

    // 2) Causal flash attention -> g_att  (grid.x = B*H, grid.y = q tiles)
    flash_kernel<<<dim3(B_ * H_, T_ / 64), 256>>>();

    // 3) Output projection: [8192,512] x [512,512]^T -> out
    gemm_out_kernel<<<dim3(D_ / 64, M_ / 64), 256>>>(w_out, out);
}

// round 2
// speedup vs baseline: 3.3685x; 3.3685x over previous
#include <cuda_runtime.h>
#include <cstdint>

// Problem constants
#define B_   2
#define T_   4096
#define D_   512
#define H_   8
#define HD_  64
#define M_   (B_ * T_)        // 8192
#define N3_  (3 * D_)         // 1536

// Scratch (static device globals — no allocation in kernel_launch)
__device__ float g_qkv[M_ * N3_];   // [8192, 1536] q|k|v
__device__ float g_att[M_ * D_];    // [8192, 512]

// ---------------------------------------------------------------------------
// tf32 helpers
// ---------------------------------------------------------------------------
__device__ __forceinline__ unsigned f2tf(float x) {
    unsigned r;
    asm("cvt.rna.tf32.f32 %0, %1;" : "=r"(r) : "f"(x));
    return r;
}
__device__ __forceinline__ float tf2f(float x) {   // store tf32 bit pattern as float
    return __uint_as_float(f2tf(x));
}

// D = A(16x8 tf32, row) * B(8x8 tf32, col) + C   (fp32 accum)
__device__ __forceinline__ void mma_tf32(float d[4], const unsigned a[4],
                                         const unsigned b[2]) {
    asm volatile(
        "mma.sync.aligned.m16n8k8.row.col.f32.tf32.tf32.f32 "
        "{%0,%1,%2,%3}, {%4,%5,%6,%7}, {%8,%9}, {%0,%1,%2,%3};\n"
        : "+f"(d[0]), "+f"(d[1]), "+f"(d[2]), "+f"(d[3])
        : "r"(a[0]), "r"(a[1]), "r"(a[2]), "r"(a[3]), "r"(b[0]), "r"(b[1]));
}

// ---------------------------------------------------------------------------
// NT GEMM with tf32 mma: C[m,n] = sum_k A[m,k]*B[n,k]
// BM=128, BN=64, BK=32, 8 warps (4x2), warp tile 32x32.
// ---------------------------------------------------------------------------
__device__ __forceinline__ void gemm_nt_mma(const float* __restrict__ A,
                                            const float* __restrict__ Bm,
                                            float* __restrict__ C,
                                            int N, int K) {
    __shared__ float As[128 * 36];   // [row][k], ld=36
    __shared__ float Bs[64 * 36];

    const int tid = threadIdx.x;
    const int w = tid >> 5;
    const int lane = tid & 31;
    const int gid = lane >> 2;
    const int tig = lane & 3;
    const int wm = w >> 1;           // 0..3
    const int wn = w & 1;            // 0..1

    const int m0 = blockIdx.y * 128;
    const int n0 = blockIdx.x * 64;

    const int lr = tid >> 3;         // 0..31
    const int lc = (tid & 7) * 4;    // 0..28

    float acc[2][4][4] = {};

    for (int k0 = 0; k0 < K; k0 += 32) {
        // global loads first (overlap with previous compute)
        float4 a4[4], b4[2];
#pragma unroll
        for (int i = 0; i < 4; ++i)
            a4[i] = *reinterpret_cast<const float4*>(
                A + (size_t)(m0 + lr + 32 * i) * K + k0 + lc);
#pragma unroll
        for (int i = 0; i < 2; ++i)
            b4[i] = *reinterpret_cast<const float4*>(
                Bm + (size_t)(n0 + lr + 32 * i) * K + k0 + lc);
        __syncthreads();
#pragma unroll
        for (int i = 0; i < 4; ++i) {
            float* p = As + (lr + 32 * i) * 36 + lc;
            p[0] = tf2f(a4[i].x); p[1] = tf2f(a4[i].y);
            p[2] = tf2f(a4[i].z); p[3] = tf2f(a4[i].w);
        }
#pragma unroll
        for (int i = 0; i < 2; ++i) {
            float* p = Bs + (lr + 32 * i) * 36 + lc;
            p[0] = tf2f(b4[i].x); p[1] = tf2f(b4[i].y);
            p[2] = tf2f(b4[i].z); p[3] = tf2f(b4[i].w);
        }
        __syncthreads();

#pragma unroll
        for (int ks = 0; ks < 4; ++ks) {
            unsigned aa[2][4], bb[4][2];
#pragma unroll
            for (int mt = 0; mt < 2; ++mt) {
                const float* p = As + (wm * 32 + mt * 16 + gid) * 36 + ks * 8 + tig;
                aa[mt][0] = __float_as_uint(p[0]);
                aa[mt][1] = __float_as_uint(p[8 * 36]);
                aa[mt][2] = __float_as_uint(p[4]);
                aa[mt][3] = __float_as_uint(p[8 * 36 + 4]);
            }
#pragma unroll
            for (int nt = 0; nt < 4; ++nt) {
                const float* p = Bs + (wn * 32 + nt * 8 + gid) * 36 + ks * 8 + tig;
                bb[nt][0] = __float_as_uint(p[0]);
                bb[nt][1] = __float_as_uint(p[4]);
            }
#pragma unroll
            for (int mt = 0; mt < 2; ++mt)
#pragma unroll
                for (int nt = 0; nt < 4; ++nt)
                    mma_tf32(acc[mt][nt], aa[mt], bb[nt]);
        }
    }

    // epilogue
#pragma unroll
    for (int mt = 0; mt < 2; ++mt) {
        const int r0 = m0 + wm * 32 + mt * 16 + gid;
#pragma unroll
        for (int nt = 0; nt < 4; ++nt) {
            const int c = n0 + wn * 32 + nt * 8 + 2 * tig;
            *reinterpret_cast<float2*>(C + (size_t)r0 * N + c) =
                make_float2(acc[mt][nt][0], acc[mt][nt][1]);
            *reinterpret_cast<float2*>(C + (size_t)(r0 + 8) * N + c) =
                make_float2(acc[mt][nt][2], acc[mt][nt][3]);
        }
    }
}

__global__ void __launch_bounds__(256)
gemm_qkv_kernel(const float* __restrict__ x, const float* __restrict__ w) {
    gemm_nt_mma(x, w, g_qkv, N3_, D_);
}

__global__ void __launch_bounds__(256)
gemm_out_kernel(const float* __restrict__ w, float* __restrict__ out) {
    gemm_nt_mma(g_att, w, out, D_, D_);
}

// ---------------------------------------------------------------------------
// Flash attention (causal) with tf32 mma.
// Block = (b, h, 128-row q tile). 8 warps x 16 q rows. BN=64 keys per iter.
// Dynamic SMEM: Ks[64][68] + Vs[64][72] + Ps[128][68]  = 70656 B.
// ---------------------------------------------------------------------------
#define LDK 68
#define LDV 72
#define LDP 68
#define FLASH_SMEM ((64 * LDK + 64 * LDV + 128 * LDP) * 4)

__global__ void __launch_bounds__(256) flash_mma_kernel() {
    extern __shared__ float sm[];
    float* Ks = sm;                       // [64][LDK]
    float* Vs = sm + 64 * LDK;            // [64][LDV]
    float* Ps = sm + 64 * LDK + 64 * LDV; // [128][LDP], warp-private strips

    const int tid = threadIdx.x;
    const int w = tid >> 5;
    const int lane = tid & 31;
    const int gid = lane >> 2;
    const int tig = lane & 3;

    const int qt = (int)gridDim.y - 1 - (int)blockIdx.y;   // heavy tiles first
    const int q0 = qt * 128;
    const int bh = blockIdx.x;
    const int b = bh >> 3;
    const int h = bh & 7;

    const float* qptr = g_qkv + (size_t)b * T_ * N3_ + h * HD_;
    const float* kptr = qptr + D_;
    const float* vptr = qptr + 2 * D_;

    const int lr = tid >> 4;          // 0..15
    const int lc = (tid & 15) * 4;    // 0..60

    // Stage Q (pre-scaled, tf32) into Ps, then pull warp fragments
#pragma unroll
    for (int rr = lr; rr < 128; rr += 16) {
        const float4 v = *reinterpret_cast<const float4*>(
            qptr + (size_t)(q0 + rr) * N3_ + lc);
        float* p = Ps + rr * LDP + lc;
        p[0] = tf2f(v.x * 0.125f); p[1] = tf2f(v.y * 0.125f);
        p[2] = tf2f(v.z * 0.125f); p[3] = tf2f(v.w * 0.125f);
    }
    __syncthreads();

    unsigned qa[8][4];
    {
        const float* Pw = Ps + (w * 16) * LDP;
#pragma unroll
        for (int ks = 0; ks < 8; ++ks) {
            qa[ks][0] = __float_as_uint(Pw[gid * LDP + ks * 8 + tig]);
            qa[ks][1] = __float_as_uint(Pw[(gid + 8) * LDP + ks * 8 + tig]);
            qa[ks][2] = __float_as_uint(Pw[gid * LDP + ks * 8 + tig + 4]);
            qa[ks][3] = __float_as_uint(Pw[(gid + 8) * LDP + ks * 8 + tig + 4]);
        }
    }

    float oc[8][4] = {};
    float mi0 = -1e30f, mi1 = -1e30f, li0 = 0.0f, li1 = 0.0f;

    const int rowlo = q0 + w * 16;    // min global q-row this warp owns
    const int niter = 2 * qt + 2;

    for (int it = 0; it < niter; ++it) {
        const int j0 = it * 64;
        __syncthreads();   // all warps done reading previous Ks/Vs

        // cooperative K/V tile load (tf32 in smem)
#pragma unroll
        for (int rr = lr; rr < 64; rr += 16) {
            const float4 kv = *reinterpret_cast<const float4*>(
                kptr + (size_t)(j0 + rr) * N3_ + lc);
            const float4 vv = *reinterpret_cast<const float4*>(
                vptr + (size_t)(j0 + rr) * N3_ + lc);
            float* pk = Ks + rr * LDK + lc;
            pk[0] = tf2f(kv.x); pk[1] = tf2f(kv.y);
            pk[2] = tf2f(kv.z); pk[3] = tf2f(kv.w);
            float* pv = Vs + rr * LDV + lc;
            pv[0] = tf2f(vv.x); pv[1] = tf2f(vv.y);
            pv[2] = tf2f(vv.z); pv[3] = tf2f(vv.w);
        }
        __syncthreads();

        if (j0 <= rowlo + 15) {       // warp has at least one unmasked element
            // ---- S = Q K^T ----
            float sc[8][4] = {};
#pragma unroll
            for (int nt = 0; nt < 8; ++nt) {
#pragma unroll
                for (int ks = 0; ks < 8; ++ks) {
                    unsigned kb[2];
                    const float* p = Ks + (nt * 8 + gid) * LDK + ks * 8 + tig;
                    kb[0] = __float_as_uint(p[0]);
                    kb[1] = __float_as_uint(p[4]);
                    mma_tf32(sc[nt], qa[ks], kb);
                }
            }

            // ---- causal mask ----
            if (j0 + 63 > rowlo) {
                const int r0 = rowlo + gid, r1 = rowlo + gid + 8;
#pragma unroll
                for (int nt = 0; nt < 8; ++nt) {
                    const int c = j0 + nt * 8 + 2 * tig;
                    if (c > r0)     sc[nt][0] = -1e30f;
                    if (c + 1 > r0) sc[nt][1] = -1e30f;
                    if (c > r1)     sc[nt][2] = -1e30f;
                    if (c + 1 > r1) sc[nt][3] = -1e30f;
                }
            }

            // ---- online softmax (rows owned by lane quads) ----
            float mx0 = -1e30f, mx1 = -1e30f;
#pragma unroll
            for (int nt = 0; nt < 8; ++nt) {
                mx0 = fmaxf(mx0, fmaxf(sc[nt][0], sc[nt][1]));
                mx1 = fmaxf(mx1, fmaxf(sc[nt][2], sc[nt][3]));
            }
            mx0 = fmaxf(mx0, __shfl_xor_sync(0xffffffffu, mx0, 1));
            mx0 = fmaxf(mx0, __shfl_xor_sync(0xffffffffu, mx0, 2));
            mx1 = fmaxf(mx1, __shfl_xor_sync(0xffffffffu, mx1, 1));
            mx1 = fmaxf(mx1, __shfl_xor_sync(0xffffffffu, mx1, 2));

            const float mn0 = fmaxf(mi0, mx0);
            const float mn1 = fmaxf(mi1, mx1);
            const float al0 = __expf(mi0 - mn0);
            const float al1 = __expf(mi1 - mn1);
            mi0 = mn0; mi1 = mn1;

            float s0 = 0.0f, s1 = 0.0f;
#pragma unroll
            for (int nt = 0; nt < 8; ++nt) {
                sc[nt][0] = __expf(sc[nt][0] - mn0);
                sc[nt][1] = __expf(sc[nt][1] - mn0);
                sc[nt][2] = __expf(sc[nt][2] - mn1);
                sc[nt][3] = __expf(sc[nt][3] - mn1);
                s0 += sc[nt][0] + sc[nt][1];
                s1 += sc[nt][2] + sc[nt][3];
            }
            s0 += __shfl_xor_sync(0xffffffffu, s0, 1);
            s0 += __shfl_xor_sync(0xffffffffu, s0, 2);
            s1 += __shfl_xor_sync(0xffffffffu, s1, 1);
            s1 += __shfl_xor_sync(0xffffffffu, s1, 2);
            li0 = li0 * al0 + s0;
            li1 = li1 * al1 + s1;
#pragma unroll
            for (int dt = 0; dt < 8; ++dt) {
                oc[dt][0] *= al0; oc[dt][1] *= al0;
                oc[dt][2] *= al1; oc[dt][3] *= al1;
            }

            // ---- P -> warp-private SMEM strip (tf32) ----
            float* Pw = Ps + (w * 16) * LDP;
#pragma unroll
            for (int nt = 0; nt < 8; ++nt) {
                const int c = nt * 8 + 2 * tig;
                Pw[gid * LDP + c]           = tf2f(sc[nt][0]);
                Pw[gid * LDP + c + 1]       = tf2f(sc[nt][1]);
                Pw[(gid + 8) * LDP + c]     = tf2f(sc[nt][2]);
                Pw[(gid + 8) * LDP + c + 1] = tf2f(sc[nt][3]);
            }
            __syncwarp();

            unsigned pa[8][4];
#pragma unroll
            for (int ks = 0; ks < 8; ++ks) {
                pa[ks][0] = __float_as_uint(Pw[gid * LDP + ks * 8 + tig]);
                pa[ks][1] = __float_as_uint(Pw[(gid + 8) * LDP + ks * 8 + tig]);
                pa[ks][2] = __float_as_uint(Pw[gid * LDP + ks * 8 + tig + 4]);
                pa[ks][3] = __float_as_uint(Pw[(gid + 8) * LDP + ks * 8 + tig + 4]);
            }

            // ---- O += P V ----
#pragma unroll
            for (int dt = 0; dt < 8; ++dt) {
#pragma unroll
                for (int ks = 0; ks < 8; ++ks) {
                    unsigned vb[2];
                    vb[0] = __float_as_uint(Vs[(ks * 8 + tig) * LDV + dt * 8 + gid]);
                    vb[1] = __float_as_uint(Vs[(ks * 8 + tig + 4) * LDV + dt * 8 + gid]);
                    mma_tf32(oc[dt], pa[ks], vb);
                }
            }
        }
    }

    // ---- epilogue ----
    const float inv0 = 1.0f / li0;
    const float inv1 = 1.0f / li1;
    const int r0 = q0 + w * 16 + gid;
    float* out0 = g_att + ((size_t)(b * T_ + r0)) * D_ + h * HD_;
    float* out1 = g_att + ((size_t)(b * T_ + r0 + 8)) * D_ + h * HD_;
#pragma unroll
    for (int dt = 0; dt < 8; ++dt) {
        const int c = dt * 8 + 2 * tig;
        *reinterpret_cast<float2*>(out0 + c) =
            make_float2(oc[dt][0] * inv0, oc[dt][1] * inv0);
        *reinterpret_cast<float2*>(out1 + c) =
            make_float2(oc[dt][2] * inv1, oc[dt][3] * inv1);
    }
}

// ---------------------------------------------------------------------------
extern "C" void kernel_launch(void* const* d_in, const int* in_sizes, int n_in,
                              void* d_out, int out_size) {
    const float* x = nullptr;
    const float* w_qkv = nullptr;
    const float* w_out = nullptr;
    for (int i = 0; i < n_in; ++i) {
        if (in_sizes[i] == M_ * D_)       x = (const float*)d_in[i];
        else if (in_sizes[i] == N3_ * D_) w_qkv = (const float*)d_in[i];
        else if (in_sizes[i] == D_ * D_)  w_out = (const float*)d_in[i];
    }
    float* out = (float*)d_out;

    static bool attr_set = false;
    if (!attr_set) {
        cudaFuncSetAttribute(flash_mma_kernel,
                             cudaFuncAttributeMaxDynamicSharedMemorySize,
                             FLASH_SMEM);
        attr_set = true;
    }

    // 1) QKV projection
    gemm_qkv_kernel<<<dim3(N3_ / 64, M_ / 128), 256>>>(x, w_qkv);

    // 2) Causal flash attention (tf32 mma)
    flash_mma_kernel<<<dim3(B_ * H_, T_ / 128), 256, FLASH_SMEM>>>();

    // 3) Output projection
    gemm_out_kernel<<<dim3(D_ / 64, M_ / 128), 256>>>(w_out, out);
}